// round 3
// baseline (speedup 1.0000x reference)
#include <cuda_runtime.h>

#define FULLMASK 0xFFFFFFFFu

__device__ float g_scratch[512];
__device__ unsigned int g_ticket = 0;

// dot of two float4
__device__ __forceinline__ float d4(const float4& a, const float4& b) {
    float s = a.x * b.x;
    s = fmaf(a.y, b.y, s);
    s = fmaf(a.z, b.z, s);
    s = fmaf(a.w, b.w, s);
    return s;
}

__device__ __forceinline__ float warp_sum(float v) {
#pragma unroll
    for (int o = 16; o; o >>= 1) v += __shfl_xor_sync(FULLMASK, v, o);
    return v;
}

// soft_rank with KL regularization, strength 2.0, n = 4 (register-resident).
__device__ __forceinline__ void softrank4(const float v[4], float out[4]) {
    float th[4];
    int pi[4];
#pragma unroll
    for (int m = 0; m < 4; m++) { th[m] = v[m] * 0.5f; pi[m] = m; }

#define CSWAP(a, b)                                     \
    do {                                                \
        if (th[a] < th[b]) {                            \
            float tf = th[a]; th[a] = th[b]; th[b] = tf;\
            int ti = pi[a]; pi[a] = pi[b]; pi[b] = ti;  \
        }                                               \
    } while (0)
    CSWAP(0, 1); CSWAP(2, 3); CSWAP(0, 2); CSWAP(1, 3); CSWAP(1, 2);
#undef CSWAP

    const float lcw00 = 1.3862943611198906f;  // log 4
    const float lcw01 = 1.9459101090932196f;  // log 7
    const float lcw02 = 2.1972245773362196f;  // log 9
    const float lcw03 = 2.302585092994046f;   // log 10
    const float lcw11 = 1.0986122886681098f;  // log 3
    const float lcw12 = 1.6094379124341003f;  // log 5
    const float lcw13 = 1.791759469228055f;   // log 6
    const float lcw22 = 0.6931471805599453f;  // log 2
    const float lcw23 = 1.0986122886681098f;  // log 3
    const float lcw33 = 0.0f;                 // log 1

    float B[4][4];
    {
        float run;
        run = 1.0f;                       B[0][0] = th[0] - lcw00;
        run += __expf(th[1] - th[0]);     B[0][1] = th[0] + __logf(run) - lcw01;
        run += __expf(th[2] - th[0]);     B[0][2] = th[0] + __logf(run) - lcw02;
        run += __expf(th[3] - th[0]);     B[0][3] = th[0] + __logf(run) - lcw03;
        run = 1.0f;                       B[1][1] = th[1] - lcw11;
        run += __expf(th[2] - th[1]);     B[1][2] = th[1] + __logf(run) - lcw12;
        run += __expf(th[3] - th[1]);     B[1][3] = th[1] + __logf(run) - lcw13;
        run = 1.0f;                       B[2][2] = th[2] - lcw22;
        run += __expf(th[3] - th[2]);     B[2][3] = th[2] + __logf(run) - lcw23;
        B[3][3] = th[3] - lcw33;
    }

    float dual[4];
    {
        float T0_3 = B[0][3], T0_2 = fmaxf(B[0][2], T0_3),
              T0_1 = fmaxf(B[0][1], T0_2), T0_0 = fmaxf(B[0][0], T0_1);
        float T1_3 = B[1][3], T1_2 = fmaxf(B[1][2], T1_3),
              T1_1 = fmaxf(B[1][1], T1_2);
        float T2_3 = B[2][3], T2_2 = fmaxf(B[2][2], T2_3);
        float T3_3 = B[3][3];
        dual[0] = T0_0;
        dual[1] = fminf(T0_1, T1_1);
        dual[2] = fminf(fminf(T0_2, T1_2), T2_2);
        dual[3] = fminf(fminf(T0_3, T1_3), fminf(T2_3, T3_3));
    }

#pragma unroll
    for (int k = 0; k < 4; k++) {
        float r = __expf(th[k] - dual[k]);
        out[0] = (pi[k] == 0) ? r : out[0];
        out[1] = (pi[k] == 1) ? r : out[1];
        out[2] = (pi[k] == 2) ? r : out[2];
        out[3] = (pi[k] == 3) ? r : out[3];
    }
}

// One block per id (512 blocks), 6 warps: warp = t*2 + h where t = feature,
// h = which half of the D=256 dims. Each warp loads 8 rows x 128 dims
// (8 x LDG.128), computes 24 partial sums (16 cross dots + 8 sq norms),
// tree-reduces them so lane k holds partial total k, then the h=0 warp
// combines the two halves via smem and finishes (distances, soft-rank,
// spearman). Single kernel: last block reduces per-block partials into out.
__global__ void __launch_bounds__(192)
cmrr_main_kernel(const float* __restrict__ f0, const float* __restrict__ f1,
                 const float* __restrict__ f2, float* __restrict__ out) {
    __shared__ float comb[3][24];   // h=1 warps' reduced partials
    __shared__ float4 rk_sh[3][8];  // normalized ranks per feature/row-slot

    const int id = blockIdx.x;           // 0..511
    const int w = threadIdx.x >> 5;      // 0..5
    const int t = w >> 1;                // feature
    const int h = w & 1;                 // D-half
    const int lane = threadIdx.x & 31;

    const int ib = id * 4;               // half-0 rows
    const int jb = 2048 + id * 4;        // half-1 rows

    const float* __restrict__ f = (t == 0) ? f0 : ((t == 1) ? f1 : f2);
    const int doff = h * 128;

    // lane owns dims [doff + lane*4 .. +3] of each row
    float4 fa[4], fb[4];
#pragma unroll
    for (int r = 0; r < 4; r++) {
        fa[r] = reinterpret_cast<const float4*>(
                    f + (size_t)(ib + r) * 256 + doff)[lane];
        fb[r] = reinterpret_cast<const float4*>(
                    f + (size_t)(jb + r) * 256 + doff)[lane];
    }

    // 24 per-lane partials: s32[r*4+c]=acc, s32[16+r]=|a_r|^2, s32[20+c]=|b_c|^2
    float s32[32];
#pragma unroll
    for (int r = 0; r < 4; r++) {
#pragma unroll
        for (int c = 0; c < 4; c++) s32[r * 4 + c] = d4(fa[r], fb[c]);
        s32[16 + r] = d4(fa[r], fa[r]);
        s32[20 + r] = d4(fb[r], fb[r]);
    }
#pragma unroll
    for (int k = 24; k < 32; k++) s32[k] = 0.0f;

    // recursive-halving tree: after 5 stages lane L holds total of value L
    float s16[16];
    {
        const bool up = (lane & 16) != 0;
#pragma unroll
        for (int k = 0; k < 16; k++) {
            float send = up ? s32[k] : s32[k + 16];
            float recv = __shfl_xor_sync(FULLMASK, send, 16);
            s16[k] = (up ? s32[k + 16] : s32[k]) + recv;
        }
    }
    float s8[8];
    {
        const bool up = (lane & 8) != 0;
#pragma unroll
        for (int k = 0; k < 8; k++) {
            float send = up ? s16[k] : s16[k + 8];
            float recv = __shfl_xor_sync(FULLMASK, send, 8);
            s8[k] = (up ? s16[k + 8] : s16[k]) + recv;
        }
    }
    float s4[4];
    {
        const bool up = (lane & 4) != 0;
#pragma unroll
        for (int k = 0; k < 4; k++) {
            float send = up ? s4[0] : s4[0];  // placeholder avoided below
            (void)send;
            float snd = up ? s8[k] : s8[k + 4];
            float recv = __shfl_xor_sync(FULLMASK, snd, 4);
            s4[k] = (up ? s8[k + 4] : s8[k]) + recv;
        }
    }
    float s2[2];
    {
        const bool up = (lane & 2) != 0;
#pragma unroll
        for (int k = 0; k < 2; k++) {
            float snd = up ? s4[k] : s4[k + 2];
            float recv = __shfl_xor_sync(FULLMASK, snd, 2);
            s2[k] = (up ? s4[k + 2] : s4[k]) + recv;
        }
    }
    float myval;
    {
        const bool up = (lane & 1) != 0;
        float snd = up ? s2[0] : s2[1];
        float recv = __shfl_xor_sync(FULLMASK, snd, 1);
        myval = (up ? s2[1] : s2[0]) + recv;
    }

    if (h == 1 && lane < 24) comb[t][lane] = myval;
    __syncthreads();

    if (h == 0) {
        float val = myval + ((lane < 24) ? comb[t][lane] : 0.0f);

        // distances on lanes 0..15: lane L = r*4+c
        float sa = __shfl_sync(FULLMASK, val, 16 + (lane >> 2));
        float sb = __shfl_sync(FULLMASK, val, 20 + (lane & 3));
        float dL = sqrtf(fmaxf(sa + sb - 2.0f * val, 1e-12f));

        // lanes 0..3: query row ib+L, v[c] = d[L][c]
        // lanes 4..7: query row jb+(L-4), v[c] = d[c][L-4]
        const int rr = lane & 3;
        const bool trans = (lane & 4) != 0;
        float v[4];
#pragma unroll
        for (int c = 0; c < 4; c++) {
            int src = trans ? (c * 4 + rr) : (rr * 4 + c);
            v[c] = __shfl_sync(FULLMASK, dL, src);
        }

        float rk[4];
        softrank4(v, rk);

        float m = 0.25f * (rk[0] + rk[1] + rk[2] + rk[3]);
        float n2 = 0.0f;
#pragma unroll
        for (int c = 0; c < 4; c++) {
            rk[c] -= m;
            n2 = fmaf(rk[c], rk[c], n2);
        }
        float inv = rsqrtf(n2);
#pragma unroll
        for (int c = 0; c < 4; c++) rk[c] *= inv;

        if (lane < 8) rk_sh[t][lane] = make_float4(rk[0], rk[1], rk[2], rk[3]);
    }
    __syncthreads();

    // warp 0 finishes the block: spearman over feature pairs, block partial,
    // and (last block only) the global reduction.
    if (w == 0) {
        float loss = 0.0f;
        if (lane < 8) {
            float4 r0 = rk_sh[0][lane];
            float4 r1 = rk_sh[1][lane];
            float4 r2 = rk_sh[2][lane];
            float sp = r0.x * r1.x + r0.y * r1.y + r0.z * r1.z + r0.w * r1.w;
            sp += r0.x * r2.x + r0.y * r2.y + r0.z * r2.z + r0.w * r2.w;
            sp += r1.x * r2.x + r1.y * r2.y + r1.z * r2.z + r1.w * r2.w;
            loss = (sp + 3.0f) * (1.0f / 6.0f);
        }
        loss += __shfl_xor_sync(FULLMASK, loss, 1);
        loss += __shfl_xor_sync(FULLMASK, loss, 2);
        loss += __shfl_xor_sync(FULLMASK, loss, 4);

        int dflag = 0;
        if (lane == 0) {
            g_scratch[id] = loss;
            __threadfence();
            unsigned int tk = atomicAdd(&g_ticket, 1u);
            dflag = (tk == 511u);
        }
        dflag = __shfl_sync(FULLMASK, dflag, 0);

        if (dflag) {
            __threadfence();  // acquire: order scratch reads after ticket
            float s = 0.0f;
#pragma unroll
            for (int k = 0; k < 16; k++)
                s += __ldcg(&g_scratch[lane + k * 32]);
            s = warp_sum(s);
            if (lane == 0) {
                out[0] = s * (1.0f / 4096.0f);
                g_ticket = 0;  // reset for next (graph-replayed) launch
            }
        }
    }
}

extern "C" void kernel_launch(void* const* d_in, const int* in_sizes, int n_in,
                              void* d_out, int out_size) {
    const float* f0 = (const float*)d_in[0];
    const float* f1 = (const float*)d_in[1];
    const float* f2 = (const float*)d_in[2];
    float* out = (float*)d_out;

    cmrr_main_kernel<<<512, 192>>>(f0, f1, f2, out);
}

// round 4
// speedup vs baseline: 1.4706x; 1.4706x over previous
#include <cuda_runtime.h>

#define FULLMASK 0xFFFFFFFFu

// Sum of squared differences of two 8-float (2x float4) chunks.
__device__ __forceinline__ float sd8(const float4& a0, const float4& a1,
                                     const float4& b0, const float4& b1) {
    float t, s;
    t = a0.x - b0.x; s = t * t;
    t = a0.y - b0.y; s = fmaf(t, t, s);
    t = a0.z - b0.z; s = fmaf(t, t, s);
    t = a0.w - b0.w; s = fmaf(t, t, s);
    t = a1.x - b1.x; s = fmaf(t, t, s);
    t = a1.y - b1.y; s = fmaf(t, t, s);
    t = a1.z - b1.z; s = fmaf(t, t, s);
    t = a1.w - b1.w; s = fmaf(t, t, s);
    return s;
}

__device__ __forceinline__ float warp_sum(float v) {
#pragma unroll
    for (int o = 16; o; o >>= 1) v += __shfl_xor_sync(FULLMASK, v, o);
    return v;
}

// soft_rank with KL regularization, strength 2.0, n = 4 (register-resident).
__device__ __forceinline__ void softrank4(const float v[4], float out[4]) {
    float th[4];
    int pi[4];
#pragma unroll
    for (int m = 0; m < 4; m++) { th[m] = v[m] * 0.5f; pi[m] = m; }

    // descending sort network on 4 elems: (0,1)(2,3)(0,2)(1,3)(1,2)
#define CSWAP(a, b)                                     \
    do {                                                \
        if (th[a] < th[b]) {                            \
            float tf = th[a]; th[a] = th[b]; th[b] = tf;\
            int ti = pi[a]; pi[a] = pi[b]; pi[b] = ti;  \
        }                                               \
    } while (0)
    CSWAP(0, 1); CSWAP(2, 3); CSWAP(0, 2); CSWAP(1, 3); CSWAP(1, 2);
#undef CSWAP

    const float lcw00 = 1.3862943611198906f;  // log 4
    const float lcw01 = 1.9459101090932196f;  // log 7
    const float lcw02 = 2.1972245773362196f;  // log 9
    const float lcw03 = 2.302585092994046f;   // log 10
    const float lcw11 = 1.0986122886681098f;  // log 3
    const float lcw12 = 1.6094379124341003f;  // log 5
    const float lcw13 = 1.791759469228055f;   // log 6
    const float lcw22 = 0.6931471805599453f;  // log 2
    const float lcw23 = 1.0986122886681098f;  // log 3
    const float lcw33 = 0.0f;                 // log 1

    // B[i][j] = LSE(th[i..j]) - log(cw[i][j]); th descending so th[i] is seg max.
    float B[4][4];
    {
        float run;
        run = 1.0f;                       B[0][0] = th[0] - lcw00;
        run += __expf(th[1] - th[0]);     B[0][1] = th[0] + __logf(run) - lcw01;
        run += __expf(th[2] - th[0]);     B[0][2] = th[0] + __logf(run) - lcw02;
        run += __expf(th[3] - th[0]);     B[0][3] = th[0] + __logf(run) - lcw03;
        run = 1.0f;                       B[1][1] = th[1] - lcw11;
        run += __expf(th[2] - th[1]);     B[1][2] = th[1] + __logf(run) - lcw12;
        run += __expf(th[3] - th[1]);     B[1][3] = th[1] + __logf(run) - lcw13;
        run = 1.0f;                       B[2][2] = th[2] - lcw22;
        run += __expf(th[3] - th[2]);     B[2][3] = th[2] + __logf(run) - lcw23;
        B[3][3] = th[3] - lcw33;
    }

    // dual[k] = min_{i<=k} max_{j>=k} B[i][j]
    float dual[4];
    {
        float T0_3 = B[0][3], T0_2 = fmaxf(B[0][2], T0_3),
              T0_1 = fmaxf(B[0][1], T0_2), T0_0 = fmaxf(B[0][0], T0_1);
        float T1_3 = B[1][3], T1_2 = fmaxf(B[1][2], T1_3),
              T1_1 = fmaxf(B[1][1], T1_2);
        float T2_3 = B[2][3], T2_2 = fmaxf(B[2][2], T2_3);
        float T3_3 = B[3][3];
        dual[0] = T0_0;
        dual[1] = fminf(T0_1, T1_1);
        dual[2] = fminf(fminf(T0_2, T1_2), T2_2);
        dual[3] = fminf(fminf(T0_3, T1_3), fminf(T2_3, T3_3));
    }

#pragma unroll
    for (int k = 0; k < 4; k++) {
        float r = __expf(th[k] - dual[k]);
        out[0] = (pi[k] == 0) ? r : out[0];
        out[1] = (pi[k] == 1) ? r : out[1];
        out[2] = (pi[k] == 2) ? r : out[2];
        out[3] = (pi[k] == 3) ? r : out[3];
    }
}

__global__ void zero_out_kernel(float* out) { out[0] = 0.0f; }

// One block per id (512 blocks), 3 warps = one per feature.
// Each warp computes the 4x4 squared-distance matrix between rows
// {id*4..+3} (half 0) and rows {2048+id*4..+3} (half 1) via direct
// sum-of-squared-differences (16 warp reductions). Rows of D give the
// soft-rank inputs for the half-0 queries; columns for half-1.
__global__ void __launch_bounds__(96)
cmrr_main_kernel(const float* __restrict__ f0, const float* __restrict__ f1,
                 const float* __restrict__ f2, float* __restrict__ out) {
    __shared__ float4 sh[3][8];  // [feature][row-slot] -> normalized ranks

    const int id = blockIdx.x;            // 0..511
    const int t = threadIdx.x >> 5;       // feature 0..2
    const int lane = threadIdx.x & 31;

    const int ib = id * 4;                // half-0 rows
    const int jb = 2048 + id * 4;         // half-1 rows

    const float* __restrict__ f = (t == 0) ? f0 : ((t == 1) ? f1 : f2);

    // Cooperative load: lane owns elems {lane*4..+3} and {(lane+32)*4..+3}
    float4 fa[4][2], fb[4][2];
#pragma unroll
    for (int r = 0; r < 4; r++) {
        const float4* pa =
            reinterpret_cast<const float4*>(f + (size_t)(ib + r) * 256);
        const float4* pb =
            reinterpret_cast<const float4*>(f + (size_t)(jb + r) * 256);
        fa[r][0] = pa[lane];
        fa[r][1] = pa[lane + 32];
        fb[r][0] = pb[lane];
        fb[r][1] = pb[lane + 32];
    }

    // d2[r][c] partial = sum over this lane's 8 dims of (a_r - b_c)^2
    float d2[4][4];
#pragma unroll
    for (int r = 0; r < 4; r++)
#pragma unroll
        for (int c = 0; c < 4; c++)
            d2[r][c] = sd8(fa[r][0], fa[r][1], fb[c][0], fb[c][1]);

    // butterfly reductions: every lane ends with the 16 full sums
#pragma unroll
    for (int r = 0; r < 4; r++)
#pragma unroll
        for (int c = 0; c < 4; c++) d2[r][c] = warp_sum(d2[r][c]);

    // lanes 0..3: query row ib+l   -> v[c] = d[l][c]
    // lanes 4..7: query row jb+(l-4) -> v[c] = d[c][l-4]
    const int rr = lane & 3;
    const bool trans = (lane & 4) != 0;
    float v[4];
#pragma unroll
    for (int c = 0; c < 4; c++) {
        float drc = (rr == 1) ? d2[1][c]
                  : (rr == 2) ? d2[2][c]
                  : (rr == 3) ? d2[3][c] : d2[0][c];
        float dcr = (rr == 1) ? d2[c][1]
                  : (rr == 2) ? d2[c][2]
                  : (rr == 3) ? d2[c][3] : d2[c][0];
        v[c] = sqrtf(fmaxf(trans ? dcr : drc, 1e-12f));
    }

    float rk[4];
    softrank4(v, rk);

    // center + normalize
    {
        float m = 0.25f * (rk[0] + rk[1] + rk[2] + rk[3]);
        float n2 = 0.0f;
#pragma unroll
        for (int c = 0; c < 4; c++) {
            rk[c] -= m;
            n2 = fmaf(rk[c], rk[c], n2);
        }
        float inv = rsqrtf(n2);
#pragma unroll
        for (int c = 0; c < 4; c++) rk[c] *= inv;
    }

    if (lane < 8) sh[t][lane] = make_float4(rk[0], rk[1], rk[2], rk[3]);
    __syncthreads();

    // warp 0: spearman across feature pairs for the 8 query rows, reduce,
    // accumulate the global mean.
    if (t == 0) {
        float loss = 0.0f;
        if (lane < 8) {
            float4 r0 = sh[0][lane];
            float4 r1 = sh[1][lane];
            float4 r2 = sh[2][lane];
            float sp = r0.x * r1.x + r0.y * r1.y + r0.z * r1.z + r0.w * r1.w;
            sp += r0.x * r2.x + r0.y * r2.y + r0.z * r2.z + r0.w * r2.w;
            sp += r1.x * r2.x + r1.y * r2.y + r1.z * r2.z + r1.w * r2.w;
            loss = (sp + 3.0f) * (1.0f / 6.0f);
        }
        loss += __shfl_xor_sync(FULLMASK, loss, 1);
        loss += __shfl_xor_sync(FULLMASK, loss, 2);
        loss += __shfl_xor_sync(FULLMASK, loss, 4);
        if (lane == 0) atomicAdd(out, loss * (1.0f / 4096.0f));
    }
}

extern "C" void kernel_launch(void* const* d_in, const int* in_sizes, int n_in,
                              void* d_out, int out_size) {
    const float* f0 = (const float*)d_in[0];
    const float* f1 = (const float*)d_in[1];
    const float* f2 = (const float*)d_in[2];
    float* out = (float*)d_out;

    zero_out_kernel<<<1, 1>>>(out);
    cmrr_main_kernel<<<512, 96>>>(f0, f1, f2, out);
}